// round 16
// baseline (speedup 1.0000x reference)
#include <cuda_runtime.h>
#include <cstdint>

// x: (32,1,64,8000) fp32, a:(64,), w:(64,)
// y[b,f,t] = | x[t] - Cw * S_t |,  S_t = sum_{d=1}^{498} a^{d-1} x_edge[t-d]
// Cw = w*(1-a)/(1-a^498), edge pad x[j<0] -> x[0]
//
// One block per QUARTER row (2000 samples + 500 halo). Early-issued TMA load,
// aligned-window warm-up, two-level combine, per-warp TMA stores.
#define T_LEN   8000
#define TILE_T  2000
#define HALO    500
#define XS_LEN  2500
#define WIN     498
#define LSUB    20
#define NSUB    100         // workers
#define NG      125         // aligned chunk sums
#define NP      121         // level-1 partials
#define BLOCK   128
// float offsets in dynamic smem
#define OFF_XS   0
#define OFF_YS   2500
#define OFF_SG   4500
#define OFF_SP   4625
#define OFF_MBAR 4748       // byte 18992: 16B-aligned
#define SMEM_BYTES (4748 * 4 + 16)

__device__ __forceinline__ float ipowf(float base, int e) {
    float p = 1.0f;
    while (e) { if (e & 1) p *= base; base *= base; e >>= 1; }
    return p;
}

__device__ __forceinline__ void mbar_wait0(uint32_t mbar) {
    uint32_t done;
    asm volatile(
        "{\n\t.reg .pred p;\n\t"
        "mbarrier.try_wait.parity.shared.b64 p, [%1], 0;\n\t"
        "selp.b32 %0, 1, 0, p;\n\t}"
        : "=r"(done) : "r"(mbar) : "memory");
    while (!done) {
        asm volatile(
            "{\n\t.reg .pred p;\n\t"
            "mbarrier.try_wait.parity.shared.b64 p, [%1], 0, 0x989680;\n\t"
            "selp.b32 %0, 1, 0, p;\n\t}"
            : "=r"(done) : "r"(mbar) : "memory");
    }
}

__global__ __launch_bounds__(BLOCK, 12)
void willmore_kernel(const float* __restrict__ x,
                     const float* __restrict__ a,
                     const float* __restrict__ w,
                     float* __restrict__ out,
                     int F) {
    extern __shared__ float sm[];
    float*  xs  = sm + OFF_XS;
    float*  ys  = sm + OFF_YS;
    float*  sG  = sm + OFF_SG;
    float*  sP  = sm + OFF_SP;
    float4* xs4 = (float4*)xs;
    const uint32_t mbar = (uint32_t)__cvta_generic_to_shared(sm + OFF_MBAR);

    const int tid    = threadIdx.x;
    const int row    = blockIdx.x >> 2;
    const int quar   = blockIdx.x & 3;
    const int t_base = quar * TILE_T;
    const int f      = row % F;
    const float* __restrict__ xrow = x + (size_t)row * T_LEN;
    float*       __restrict__ orow = out + (size_t)row * T_LEN + t_base;

    // ---- phase A: init + TMA issue by t0 BEFORE any block sync ----
    if (tid == 0) {
        asm volatile("mbarrier.init.shared.b64 [%0], 1;" :: "r"(mbar) : "memory");
        asm volatile("fence.mbarrier_init.release.cluster;" ::: "memory");
        const int   nbytes = (quar == 0) ? TILE_T * 4 : XS_LEN * 4;
        const float* src   = (quar == 0) ? xrow : (xrow + t_base - HALO);
        uint32_t dst = (uint32_t)__cvta_generic_to_shared(
                           (quar == 0) ? (xs + HALO) : xs);
        asm volatile("mbarrier.arrive.expect_tx.shared.b64 _, [%0], %1;"
                     :: "r"(mbar), "r"(nbytes) : "memory");
        asm volatile(
            "cp.async.bulk.shared::cluster.global.mbarrier::complete_tx::bytes "
            "[%0], [%1], %2, [%3];"
            :: "r"(dst), "l"(src), "r"(nbytes), "r"(mbar) : "memory");
    }

    // halo splat (disjoint from DMA destination) + constants overlap the DMA
    if (quar == 0) {
        const float x0v = __ldg(&xrow[0]);
        const float4 pad4 = make_float4(x0v, x0v, x0v, x0v);
        #pragma unroll
        for (int i = tid; i < HALO / 4; i += BLOCK)
            xs4[i] = pad4;
    }
    const float af = __ldg(&a[f]);
    const float wf = __ldg(&w[f]);
    const float p498 = ipowf(af, WIN);
    const float Cw = (1.0f - af) / (1.0f - p498) * wf;
    const float a10  = ipowf(af, 10);
    const float a20  = a10 * a10;
    const float a100 = ipowf(a20, 5);

    __syncthreads();           // mbar init + splat visible to all
    mbar_wait0(mbar);          // DMA complete
    __syncthreads();

    // ---- B1: aligned chunk sums G_k = Horner20 over xs[20k..20k+19] ----
    if (tid < NG) {
        const int b4 = 5 * tid;
        const float4 q0 = xs4[b4];
        const float4 q1 = xs4[b4 + 1];
        const float4 q2 = xs4[b4 + 2];
        const float4 q3 = xs4[b4 + 3];
        const float4 q4 = xs4[b4 + 4];
        float pA = q0.x;
        pA = fmaf(af, pA, q0.y); pA = fmaf(af, pA, q0.z); pA = fmaf(af, pA, q0.w);
        pA = fmaf(af, pA, q1.x); pA = fmaf(af, pA, q1.y);
        pA = fmaf(af, pA, q1.z); pA = fmaf(af, pA, q1.w);
        pA = fmaf(af, pA, q2.x); pA = fmaf(af, pA, q2.y);
        float pB = q2.z;
        pB = fmaf(af, pB, q2.w);
        pB = fmaf(af, pB, q3.x); pB = fmaf(af, pB, q3.y);
        pB = fmaf(af, pB, q3.z); pB = fmaf(af, pB, q3.w);
        pB = fmaf(af, pB, q4.x); pB = fmaf(af, pB, q4.y);
        pB = fmaf(af, pB, q4.z); pB = fmaf(af, pB, q4.w);
        sG[tid] = fmaf(pA, a10, pB);
    }
    __syncthreads();

    // ---- B1.5: level-1 partials sP[j] = Horner(sG[j..j+4], a^20) ----
    if (tid < NP) {
        float p = sG[tid];
        p = fmaf(a20, p, sG[tid + 1]);
        p = fmaf(a20, p, sG[tid + 2]);
        p = fmaf(a20, p, sG[tid + 3]);
        p = fmaf(a20, p, sG[tid + 4]);
        sP[tid] = p;
    }
    __syncthreads();

    // ---- B2: level-2 combine + correction + sliding recurrence ----
    if (tid < NSUB) {
        float W = sP[tid];
        W = fmaf(a100, W, sP[tid + 5]);
        W = fmaf(a100, W, sP[tid + 10]);
        W = fmaf(a100, W, sP[tid + 15]);
        W = fmaf(a100, W, sP[tid + 20]);

        const int q0i = 5 * tid;               // float4 index of window start
        float4* ys4 = (float4*)ys;
        float4 mA = xs4[q0i];                  // own-window quad 0
        // S = W - p498*(x[t0-499] + a*x[t0-500]) = W - p498*(mA.y + a*mA.x)
        float S = fmaf(-p498, fmaf(af, mA.x, mA.y), W);

        #pragma unroll
        for (int j = 0; j < 5; ++j) {
            const float4 mB = xs4[q0i + j + 1];
            const float4 xt = xs4[125 + q0i + j];   // xs[500 + 20i + 4j ..]
            float4 yv;
            yv.x = fabsf(fmaf(-Cw, S, xt.x));
            S = fmaf(af, S, fmaf(-p498, mA.z, xt.x));
            yv.y = fabsf(fmaf(-Cw, S, xt.y));
            S = fmaf(af, S, fmaf(-p498, mA.w, xt.y));
            yv.z = fabsf(fmaf(-Cw, S, xt.z));
            S = fmaf(af, S, fmaf(-p498, mB.x, xt.z));
            yv.w = fabsf(fmaf(-Cw, S, xt.w));
            S = fmaf(af, S, fmaf(-p498, mB.y, xt.w));
            ys4[q0i + j] = yv;
            mA = mB;
        }
    }

    // ---- phase C: per-warp TMA store of this warp's own ys slice ----
    // warp w's workers are exactly threads 32w..32w+31 -> ys[640w..640w+639]
    __syncwarp();
    {
        const int wid = tid >> 5;
        const int y0  = wid * 640;                       // first float of slice
        const int nby = (wid < 3) ? 2560 : (TILE_T - 1920) * 4;  // 2560 / 320
        if ((tid & 31) == 0) {
            uint32_t src = (uint32_t)__cvta_generic_to_shared(ys + y0);
            asm volatile("fence.proxy.async.shared::cta;" ::: "memory");
            asm volatile("cp.async.bulk.global.shared::cta.bulk_group [%0], [%1], %2;"
                         :: "l"(orow + y0), "r"(src), "r"(nby) : "memory");
            asm volatile("cp.async.bulk.commit_group;" ::: "memory");
            asm volatile("cp.async.bulk.wait_group.read 0;" ::: "memory");
        }
    }
}

extern "C" void kernel_launch(void* const* d_in, const int* in_sizes, int n_in,
                              void* d_out, int out_size) {
    const float* x = (const float*)d_in[0];
    const float* a = (const float*)d_in[1];
    const float* w = (const float*)d_in[2];
    float* out = (float*)d_out;

    const int F = in_sizes[1];                 // 64
    const int rows = in_sizes[0] / T_LEN;      // 2048

    cudaFuncSetAttribute(willmore_kernel,
                         cudaFuncAttributeMaxDynamicSharedMemorySize, SMEM_BYTES);
    willmore_kernel<<<rows * 4, BLOCK, SMEM_BYTES>>>(x, a, w, out, F);
}

// round 17
// speedup vs baseline: 1.0751x; 1.0751x over previous
#include <cuda_runtime.h>
#include <cstdint>

// x: (32,1,64,8000) fp32, a:(64,), w:(64,)
// y[b,f,t] = | x[t] - Cw * S_t |,  S_t = sum_{d=1}^{498} a^{d-1} x_edge[t-d]
// Cw = w*(1-a)/(1-a^498), edge pad x[j<0] -> x[0]
//
// One block per QUARTER row (2000 samples + 500 halo). Early-issued TMA load,
// aligned-window warm-up, two-level combine, single contiguous TMA store.
#define T_LEN   8000
#define TILE_T  2000
#define HALO    500
#define XS_LEN  2500
#define WIN     498
#define LSUB    20
#define NSUB    100         // workers
#define NG      125         // aligned chunk sums
#define NP      121         // level-1 partials
#define BLOCK   128
// float offsets in dynamic smem
#define OFF_XS   0
#define OFF_YS   2500
#define OFF_SG   4500
#define OFF_SP   4625
#define OFF_MBAR 4748       // byte 18992: 16B-aligned
#define SMEM_BYTES (4748 * 4 + 16)

__device__ __forceinline__ float ipowf(float base, int e) {
    float p = 1.0f;
    while (e) { if (e & 1) p *= base; base *= base; e >>= 1; }
    return p;
}

__device__ __forceinline__ void mbar_wait0(uint32_t mbar) {
    uint32_t done;
    asm volatile(
        "{\n\t.reg .pred p;\n\t"
        "mbarrier.try_wait.parity.shared.b64 p, [%1], 0;\n\t"
        "selp.b32 %0, 1, 0, p;\n\t}"
        : "=r"(done) : "r"(mbar) : "memory");
    while (!done) {
        asm volatile(
            "{\n\t.reg .pred p;\n\t"
            "mbarrier.try_wait.parity.shared.b64 p, [%1], 0, 0x989680;\n\t"
            "selp.b32 %0, 1, 0, p;\n\t}"
            : "=r"(done) : "r"(mbar) : "memory");
    }
}

__global__ __launch_bounds__(BLOCK, 12)
void willmore_kernel(const float* __restrict__ x,
                     const float* __restrict__ a,
                     const float* __restrict__ w,
                     float* __restrict__ out,
                     int F) {
    extern __shared__ float sm[];
    float*  xs  = sm + OFF_XS;
    float*  ys  = sm + OFF_YS;
    float*  sG  = sm + OFF_SG;
    float*  sP  = sm + OFF_SP;
    float4* xs4 = (float4*)xs;
    const uint32_t mbar = (uint32_t)__cvta_generic_to_shared(sm + OFF_MBAR);

    const int tid    = threadIdx.x;
    const int row    = blockIdx.x >> 2;
    const int quar   = blockIdx.x & 3;
    const int t_base = quar * TILE_T;
    const int f      = row % F;
    const float* __restrict__ xrow = x + (size_t)row * T_LEN;
    float*       __restrict__ orow = out + (size_t)row * T_LEN + t_base;

    // ---- phase A: init + TMA issue by t0 BEFORE any block sync ----
    if (tid == 0) {
        asm volatile("mbarrier.init.shared.b64 [%0], 1;" :: "r"(mbar) : "memory");
        asm volatile("fence.mbarrier_init.release.cluster;" ::: "memory");
        const int   nbytes = (quar == 0) ? TILE_T * 4 : XS_LEN * 4;
        const float* src   = (quar == 0) ? xrow : (xrow + t_base - HALO);
        uint32_t dst = (uint32_t)__cvta_generic_to_shared(
                           (quar == 0) ? (xs + HALO) : xs);
        asm volatile("mbarrier.arrive.expect_tx.shared.b64 _, [%0], %1;"
                     :: "r"(mbar), "r"(nbytes) : "memory");
        asm volatile(
            "cp.async.bulk.shared::cluster.global.mbarrier::complete_tx::bytes "
            "[%0], [%1], %2, [%3];"
            :: "r"(dst), "l"(src), "r"(nbytes), "r"(mbar) : "memory");
    }

    // halo splat (disjoint from DMA destination) + constants overlap the DMA
    if (quar == 0) {
        const float x0v = __ldg(&xrow[0]);
        const float4 pad4 = make_float4(x0v, x0v, x0v, x0v);
        #pragma unroll
        for (int i = tid; i < HALO / 4; i += BLOCK)
            xs4[i] = pad4;
    }
    const float af = __ldg(&a[f]);
    const float wf = __ldg(&w[f]);
    const float p498 = ipowf(af, WIN);
    const float Cw = (1.0f - af) / (1.0f - p498) * wf;
    const float a10  = ipowf(af, 10);
    const float a20  = a10 * a10;
    const float a100 = ipowf(a20, 5);

    __syncthreads();           // mbar init + splat visible to all
    mbar_wait0(mbar);          // every thread waits -> DMA visible, no 2nd sync

    // ---- B1: aligned chunk sums G_k = Horner20 over xs[20k..20k+19] ----
    if (tid < NG) {
        const int b4 = 5 * tid;
        const float4 q0 = xs4[b4];
        const float4 q1 = xs4[b4 + 1];
        const float4 q2 = xs4[b4 + 2];
        const float4 q3 = xs4[b4 + 3];
        const float4 q4 = xs4[b4 + 4];
        float pA = q0.x;
        pA = fmaf(af, pA, q0.y); pA = fmaf(af, pA, q0.z); pA = fmaf(af, pA, q0.w);
        pA = fmaf(af, pA, q1.x); pA = fmaf(af, pA, q1.y);
        pA = fmaf(af, pA, q1.z); pA = fmaf(af, pA, q1.w);
        pA = fmaf(af, pA, q2.x); pA = fmaf(af, pA, q2.y);
        float pB = q2.z;
        pB = fmaf(af, pB, q2.w);
        pB = fmaf(af, pB, q3.x); pB = fmaf(af, pB, q3.y);
        pB = fmaf(af, pB, q3.z); pB = fmaf(af, pB, q3.w);
        pB = fmaf(af, pB, q4.x); pB = fmaf(af, pB, q4.y);
        pB = fmaf(af, pB, q4.z); pB = fmaf(af, pB, q4.w);
        sG[tid] = fmaf(pA, a10, pB);
    }
    __syncthreads();

    // ---- B1.5: level-1 partials sP[j] = Horner(sG[j..j+4], a^20) ----
    if (tid < NP) {
        float p = sG[tid];
        p = fmaf(a20, p, sG[tid + 1]);
        p = fmaf(a20, p, sG[tid + 2]);
        p = fmaf(a20, p, sG[tid + 3]);
        p = fmaf(a20, p, sG[tid + 4]);
        sP[tid] = p;
    }
    __syncthreads();

    // ---- B2: level-2 combine + correction + sliding recurrence ----
    if (tid < NSUB) {
        float W = sP[tid];
        W = fmaf(a100, W, sP[tid + 5]);
        W = fmaf(a100, W, sP[tid + 10]);
        W = fmaf(a100, W, sP[tid + 15]);
        W = fmaf(a100, W, sP[tid + 20]);

        const int q0i = 5 * tid;               // float4 index of window start
        float4* ys4 = (float4*)ys;
        float4 mA = xs4[q0i];                  // own-window quad 0
        // S = W - p498*(x[t0-499] + a*x[t0-500]) = W - p498*(mA.y + a*mA.x)
        float S = fmaf(-p498, fmaf(af, mA.x, mA.y), W);

        #pragma unroll
        for (int j = 0; j < 5; ++j) {
            const float4 mB = xs4[q0i + j + 1];
            const float4 xt = xs4[125 + q0i + j];   // xs[500 + 20i + 4j ..]
            float4 yv;
            yv.x = fabsf(fmaf(-Cw, S, xt.x));
            S = fmaf(af, S, fmaf(-p498, mA.z, xt.x));
            yv.y = fabsf(fmaf(-Cw, S, xt.y));
            S = fmaf(af, S, fmaf(-p498, mA.w, xt.y));
            yv.z = fabsf(fmaf(-Cw, S, xt.z));
            S = fmaf(af, S, fmaf(-p498, mB.x, xt.z));
            yv.w = fabsf(fmaf(-Cw, S, xt.w));
            S = fmaf(af, S, fmaf(-p498, mB.y, xt.w));
            ys4[q0i + j] = yv;
            mA = mB;
        }
    }
    __syncthreads();

    // ---- phase C: single contiguous TMA store ----
    if (tid == 0) {
        uint32_t src = (uint32_t)__cvta_generic_to_shared(ys);
        asm volatile("fence.proxy.async.shared::cta;" ::: "memory");
        asm volatile("cp.async.bulk.global.shared::cta.bulk_group [%0], [%1], %2;"
                     :: "l"(orow), "r"(src), "r"(TILE_T * 4) : "memory");
        asm volatile("cp.async.bulk.commit_group;" ::: "memory");
        asm volatile("cp.async.bulk.wait_group.read 0;" ::: "memory");
    }
}

extern "C" void kernel_launch(void* const* d_in, const int* in_sizes, int n_in,
                              void* d_out, int out_size) {
    const float* x = (const float*)d_in[0];
    const float* a = (const float*)d_in[1];
    const float* w = (const float*)d_in[2];
    float* out = (float*)d_out;

    const int F = in_sizes[1];                 // 64
    const int rows = in_sizes[0] / T_LEN;      // 2048

    cudaFuncSetAttribute(willmore_kernel,
                         cudaFuncAttributeMaxDynamicSharedMemorySize, SMEM_BYTES);
    willmore_kernel<<<rows * 4, BLOCK, SMEM_BYTES>>>(x, a, w, out, F);
}